// round 2
// baseline (speedup 1.0000x reference)
#include <cuda_runtime.h>
#include <cuda_bf16.h>
#include <cstdint>

// Problem constants (fixed by the reference: B=64, T=512, D=768, C=31)
#define B_DIM 64
#define T_DIM 512
#define D_DIM 768
#define C_DIM 31
#define NSEG  (C_DIM + 1)       // 32 segments per batch
#define CHUNK 32                // tokens staged in SMEM per online-softmax step
#define NTHREADS 256
// D_DIM / NTHREADS = 3 columns per thread

// Dynamic SMEM layout (floats):
//   tile  : CHUNK * D_DIM   (24576)
//   w5s   : D_DIM           (768)
//   sc    : CHUNK           (32)   per-chunk raw scores
//   wts   : CHUNK           (32)   per-chunk exp weights
//   st    : 4                      [0]=rescale, [1]=running l, [2]=running m
#define SMEM_FLOATS (CHUNK * D_DIM + D_DIM + CHUNK + CHUNK + 4)
#define SMEM_BYTES  (SMEM_FLOATS * 4)

__global__ __launch_bounds__(NTHREADS, 2)
void seg_softmax_pool(const float* __restrict__ h,
                      const int*   __restrict__ clause_b,
                      const float* __restrict__ w5,
                      const float* __restrict__ b5,
                      float*       __restrict__ out)
{
    const int j   = blockIdx.x;   // segment index 0..31
    const int b   = blockIdx.y;   // batch index
    const int tid = threadIdx.x;
    const int wid = tid >> 5;
    const int lane = tid & 31;

    extern __shared__ float smem[];
    float* tile = smem;                       // [CHUNK][D_DIM]
    float* w5s  = tile + CHUNK * D_DIM;       // [D_DIM]
    float* sc   = w5s + D_DIM;                // [CHUNK]
    float* wts  = sc + CHUNK;                 // [CHUNK]
    float* st   = wts + CHUNK;                // [4]

    // Stage w5 and init softmax state
    for (int d = tid; d < D_DIM; d += NTHREADS) w5s[d] = w5[d];
    if (tid == 0) { st[1] = 0.0f; st[2] = -3.4e38f; }

    // Segment bounds (segments partition [0,T))
    const int start = (j == 0)     ? 0      : clause_b[b * C_DIM + j - 1];
    const int end   = (j == C_DIM) ? T_DIM  : clause_b[b * C_DIM + j];
    const float bias = b5[0];

    float acc0 = 0.0f, acc1 = 0.0f, acc2 = 0.0f;

    for (int t0 = start; t0 < end; t0 += CHUNK) {
        const int clen = min(CHUNK, end - t0);

        __syncthreads();  // protect tile/sc/wts/st from previous-iteration readers
                          // (also orders the w5s/st init on the first pass)

        // ---- Stage h[b, t0 : t0+clen, :] into SMEM (contiguous, float4) ----
        {
            const float4* __restrict__ src =
                (const float4*)(h + ((size_t)b * T_DIM + t0) * D_DIM);
            float4* dst = (float4*)tile;
            const int n4 = clen * (D_DIM / 4);
            #pragma unroll 4
            for (int i = tid; i < n4; i += NTHREADS) dst[i] = src[i];
        }
        __syncthreads();

        // ---- Scores: one warp per token, lane-strided dot with w5 ----
        for (int t = wid; t < clen; t += NTHREADS / 32) {
            const float* row = tile + t * D_DIM;
            float s = 0.0f;
            #pragma unroll
            for (int i = lane; i < D_DIM; i += 32) s += row[i] * w5s[i];
            #pragma unroll
            for (int o = 16; o > 0; o >>= 1) s += __shfl_xor_sync(0xFFFFFFFFu, s, o);
            if (lane == 0) sc[t] = s + bias;
        }
        __syncthreads();

        // ---- Warp 0: online-softmax bookkeeping for this chunk ----
        if (wid == 0) {
            float s = (lane < clen) ? sc[lane] : -3.4e38f;
            float mc = s;
            #pragma unroll
            for (int o = 16; o > 0; o >>= 1)
                mc = fmaxf(mc, __shfl_xor_sync(0xFFFFFFFFu, mc, o));
            const float m_old = st[2];
            const float m_new = fmaxf(m_old, mc);
            const float w = (lane < clen) ? __expf(s - m_new) : 0.0f;
            wts[lane] = w;
            float csum = w;
            #pragma unroll
            for (int o = 16; o > 0; o >>= 1)
                csum += __shfl_xor_sync(0xFFFFFFFFu, csum, o);
            if (lane == 0) {
                const float rescale = __expf(m_old - m_new);  // 0 on first chunk
                st[0] = rescale;
                st[1] = st[1] * rescale + csum;
                st[2] = m_new;
            }
        }
        __syncthreads();

        // ---- Weighted accumulation (3 columns per thread, conflict-free LDS) ----
        {
            const float rescale = st[0];
            acc0 *= rescale; acc1 *= rescale; acc2 *= rescale;
            for (int t = 0; t < clen; ++t) {
                const float w = wts[t];
                const float* row = tile + t * D_DIM;
                acc0 = fmaf(w, row[tid],           acc0);
                acc1 = fmaf(w, row[tid + 256],     acc1);
                acc2 = fmaf(w, row[tid + 512],     acc2);
            }
        }
    }

    __syncthreads();  // make sure st[1] final value is visible (it is: last writer
                      // sync'd above, but keep ordering explicit)
    const float inv = 1.0f / st[1];
    const size_t o = ((size_t)b * NSEG + j) * (size_t)D_DIM + tid;
    out[o]       = acc0 * inv;
    out[o + 256] = acc1 * inv;
    out[o + 512] = acc2 * inv;
}

extern "C" void kernel_launch(void* const* d_in, const int* in_sizes, int n_in,
                              void* d_out, int out_size)
{
    const float* h        = (const float*)d_in[0];   // [B, T, D] f32
    const int*   clause_b = (const int*)  d_in[1];   // [B, C] int32
    const float* w5       = (const float*)d_in[2];   // [D, 1] f32
    const float* b5       = (const float*)d_in[3];   // [1] f32
    float* out            = (float*)d_out;           // [B, NSEG, D] f32

    // Opt in to >48KB dynamic SMEM (idempotent; host-side attribute, capture-safe)
    cudaFuncSetAttribute(seg_softmax_pool,
                         cudaFuncAttributeMaxDynamicSharedMemorySize, SMEM_BYTES);

    dim3 grid(NSEG, B_DIM);
    seg_softmax_pool<<<grid, NTHREADS, SMEM_BYTES>>>(h, clause_b, w5, b5, out);
}

// round 3
// speedup vs baseline: 1.3398x; 1.3398x over previous
#include <cuda_runtime.h>
#include <cuda_bf16.h>
#include <cstdint>

// Problem constants (fixed by the reference: B=64, T=512, D=768, C=31)
#define B_DIM 64
#define T_DIM 512
#define D_DIM 768
#define C_DIM 31
#define NSEG  (C_DIM + 1)          // 32 segments per batch (they partition [0,T))
#define NQ    (D_DIM / 128)        // 6 float4 per lane (768 = 32 lanes * 6 * 4)
#define WARPS_PER_CTA 4
#define NTHREADS (WARPS_PER_CTA * 32)

// One warp per (batch, segment). Online softmax => each row of h is loaded
// from global exactly once, into registers, and reused for the score dot and
// the weighted accumulation. No __syncthreads in the main loop, no SMEM tile.
__global__ __launch_bounds__(NTHREADS, 5)
void seg_pool_warp(const float* __restrict__ h,
                   const int*   __restrict__ clause_b,
                   const float* __restrict__ w5,
                   const float* __restrict__ b5,
                   float*       __restrict__ out)
{
    const int lane = threadIdx.x & 31;
    const int widx = blockIdx.x * WARPS_PER_CTA + (threadIdx.x >> 5);
    const int b = widx >> 5;        // widx / NSEG
    const int j = widx & (NSEG - 1);

    // Stage w5 once per CTA (lane-distinct float4 reads later: conflict-free)
    __shared__ float w5s[D_DIM];
    for (int i = threadIdx.x; i < D_DIM; i += NTHREADS) w5s[i] = w5[i];
    __syncthreads();

    // Segment bounds (segments partition [0,T))
    const int start = (j == 0)     ? 0     : clause_b[b * C_DIM + j - 1];
    const int end   = (j == C_DIM) ? T_DIM : clause_b[b * C_DIM + j];
    const float bias = b5[0];

    const float4* __restrict__ h4 =
        (const float4*)(h + (size_t)b * T_DIM * D_DIM);
    const float4* __restrict__ w4 = (const float4*)w5s;

    float4 acc[NQ];
    #pragma unroll
    for (int q = 0; q < NQ; ++q) acc[q] = make_float4(0.f, 0.f, 0.f, 0.f);
    float m = -3.4e38f, l = 0.f;

    float4 v[NQ], vn[NQ];

    // Preload first token's row
    {
        const float4* row = h4 + (size_t)start * (D_DIM / 4) + lane;
        #pragma unroll
        for (int q = 0; q < NQ; ++q) v[q] = __ldg(row + 32 * q);
    }

    for (int t = start; t < end; ++t) {
        // Prefetch next token (warp-uniform predicate) to overlap DRAM latency
        // with the shuffle-reduce / MUFU chain below.
        if (t + 1 < end) {
            const float4* rn = h4 + (size_t)(t + 1) * (D_DIM / 4) + lane;
            #pragma unroll
            for (int q = 0; q < NQ; ++q) vn[q] = __ldg(rn + 32 * q);
        }

        // ---- score: dot(row, w5) ----
        float s = 0.f;
        #pragma unroll
        for (int q = 0; q < NQ; ++q) {
            const float4 w = w4[lane + 32 * q];
            s = fmaf(v[q].x, w.x, s);
            s = fmaf(v[q].y, w.y, s);
            s = fmaf(v[q].z, w.z, s);
            s = fmaf(v[q].w, w.w, s);
        }
        #pragma unroll
        for (int o = 16; o > 0; o >>= 1) s += __shfl_xor_sync(0xFFFFFFFFu, s, o);
        s += bias;

        // ---- online softmax update ----
        const float m_new = fmaxf(m, s);
        const float r = __expf(m - m_new);   // 0 on first token (exp(-inf))
        const float w = __expf(s - m_new);
        l = fmaf(l, r, w);
        m = m_new;

        #pragma unroll
        for (int q = 0; q < NQ; ++q) {
            acc[q].x = fmaf(acc[q].x, r, w * v[q].x);
            acc[q].y = fmaf(acc[q].y, r, w * v[q].y);
            acc[q].z = fmaf(acc[q].z, r, w * v[q].z);
            acc[q].w = fmaf(acc[q].w, r, w * v[q].w);
        }

        #pragma unroll
        for (int q = 0; q < NQ; ++q) v[q] = vn[q];
    }

    // ---- normalize + store (coalesced STG.128) ----
    const float inv = __fdividef(1.f, l);
    float4* o4 = (float4*)(out + ((size_t)b * NSEG + j) * (size_t)D_DIM);
    #pragma unroll
    for (int q = 0; q < NQ; ++q) {
        float4 r4;
        r4.x = acc[q].x * inv;
        r4.y = acc[q].y * inv;
        r4.z = acc[q].z * inv;
        r4.w = acc[q].w * inv;
        o4[lane + 32 * q] = r4;
    }
}

extern "C" void kernel_launch(void* const* d_in, const int* in_sizes, int n_in,
                              void* d_out, int out_size)
{
    const float* h        = (const float*)d_in[0];   // [B, T, D] f32
    const int*   clause_b = (const int*)  d_in[1];   // [B, C] int32
    const float* w5       = (const float*)d_in[2];   // [D, 1] f32
    const float* b5       = (const float*)d_in[3];   // [1] f32
    float* out            = (float*)d_out;           // [B, NSEG, D] f32

    const int total_warps = B_DIM * NSEG;            // 2048
    const int blocks = total_warps / WARPS_PER_CTA;  // 512
    seg_pool_warp<<<blocks, NTHREADS>>>(h, clause_b, w5, b5, out);
}